// round 15
// baseline (speedup 1.0000x reference)
#include <cuda_runtime.h>
#include <cuda_fp16.h>

// Problem constants
#define N_NODES   100000
#define N_EDGES   1600000
#define E_TOT     (N_EDGES + N_NODES)   // with self-loops
#define N_FEAT    128
#define N_CLASSES 10
#define N_GRAPHS  256

#define SCAN_B    512
#define NB_SCAN   ((N_NODES + SCAN_B - 1) / SCAN_B)   // 196

// ---------------- device scratch ----------------
__device__ __align__(16) __half d_h1h[N_NODES * 64];    // layer1 features (gather-only)
__device__ __align__(16) float  d_als1[N_NODES * 8];
__device__ __align__(16) float  d_ald1[N_NODES * 8];
__device__ __align__(16) __half d_out1h[N_NODES * 64];  // layer1 output (k5 input, fp16)
__device__ __align__(16) __half d_h2h[N_NODES * 128];   // layer2 features (gather-only)
__device__ __align__(16) float  d_als2[N_NODES];
__device__ __align__(16) float  d_ald2[N_NODES];
__device__ __align__(16) float  d_out2[N_NODES * 128];

// CSR scratch
__device__ int d_deg   [N_NODES];
__device__ int d_rowptr[N_NODES + 1];
__device__ int d_wofs  [N_NODES];
__device__ int d_esrc  [E_TOT];

__device__ __forceinline__ float lrelu(float v) { return v > 0.f ? v : 0.2f * v; }

// ================= CSR build =================
__global__ void k_zero_deg() {
    int i = blockIdx.x * SCAN_B + threadIdx.x;
    if (i < N_NODES) d_deg[i] = 0;
}

__global__ void k_hist(const int* __restrict__ ei) {
    int i = blockIdx.x * 256 + threadIdx.x;
    int e = i * 2;
    if (e >= N_EDGES) return;
    int2 d = *(const int2*)(ei + N_EDGES + e);
    atomicAdd(&d_deg[d.x], 1);
    atomicAdd(&d_deg[d.y], 1);
}

// Single-block full scan: deg(+1 self-loop) -> rowptr & wofs.
__global__ __launch_bounds__(SCAN_B) void k_scan_all() {
    __shared__ int s[SCAN_B];
    int t = threadIdx.x;
    const int CH = (N_NODES + SCAN_B - 1) / SCAN_B;   // 196
    int i0 = t * CH;
    int i1 = min(i0 + CH, N_NODES);
    int run = 0;
    for (int i = i0; i < i1; i++) {
        run += d_deg[i] + 1;          // +1 = self-loop
        d_rowptr[i + 1] = run;        // thread-local inclusive prefix
    }
    s[t] = run;
    __syncthreads();
#pragma unroll
    for (int off = 1; off < SCAN_B; off <<= 1) {
        int u = (t >= off) ? s[t - off] : 0;
        __syncthreads();
        s[t] += u;
        __syncthreads();
    }
    int ofs = s[t] - run;             // exclusive prefix for this thread's chunk
    for (int i = i0; i < i1; i++) {
        int v = d_rowptr[i + 1] + ofs;
        d_rowptr[i + 1] = v;
        if (i + 1 < N_NODES) d_wofs[i + 1] = v;
    }
    if (t == 0) { d_rowptr[0] = 0; d_wofs[0] = 0; }
}

__global__ void k_scatter(const int* __restrict__ ei) {
    int i = blockIdx.x * 256 + threadIdx.x;
    int e = i * 2;
    if (e < N_EDGES) {
        int2 sv = *(const int2*)(ei + e);
        int2 dv = *(const int2*)(ei + N_EDGES + e);
        int p0 = atomicAdd(&d_wofs[dv.x], 1);
        d_esrc[p0] = sv.x;
        int p1 = atomicAdd(&d_wofs[dv.y], 1);
        d_esrc[p1] = sv.y;
    } else {
        int n = i - N_EDGES / 2;
        if (n < N_NODES) {
            int p = atomicAdd(&d_wofs[n], 1);
            d_esrc[p] = n;
        }
    }
}

// ================= K1: h1 = x @ W1 (100000x128 @ 128x64), register-tiled =================
#define RPB1 64
__global__ __launch_bounds__(256) void k1_gemm(const float* __restrict__ x,
                                               const float* __restrict__ W1,
                                               const float* __restrict__ a_src1,
                                               const float* __restrict__ a_dst1) {
    __shared__ float xs[RPB1][64];
    __shared__ float Ws[64][64];
    int t  = threadIdx.x;
    int nb = blockIdx.x * RPB1;
    int tr = t >> 4;
    int tc = t & 15;
    float acc[4][4];
#pragma unroll
    for (int r = 0; r < 4; r++)
#pragma unroll
        for (int c = 0; c < 4; c++) acc[r][c] = 0.f;

    for (int p = 0; p < 2; p++) {
        __syncthreads();
        {
            int nl = t >> 2;
            int j0 = (t & 3) * 4;
            int n = nb + nl;
            float4* xd = (float4*)&xs[nl][0];
            if (n < N_NODES) {
                const float4* xg = (const float4*)(x + n * 128 + p * 64);
#pragma unroll
                for (int j = 0; j < 4; j++) xd[j0 + j] = xg[j0 + j];
            } else {
                float4 z = make_float4(0.f, 0.f, 0.f, 0.f);
#pragma unroll
                for (int j = 0; j < 4; j++) xd[j0 + j] = z;
            }
            const float4* Wg = (const float4*)(W1 + (p * 64) * 64);
            float4* Wd = (float4*)&Ws[0][0];
            for (int i = t; i < 64 * 64 / 4; i += 256) Wd[i] = Wg[i];
        }
        __syncthreads();
#pragma unroll 2
        for (int kk = 0; kk < 64; kk++) {
            float4 wv = *(const float4*)&Ws[kk][tc * 4];
            float x0 = xs[tr * 4 + 0][kk];
            float x1 = xs[tr * 4 + 1][kk];
            float x2 = xs[tr * 4 + 2][kk];
            float x3 = xs[tr * 4 + 3][kk];
            acc[0][0] += x0 * wv.x; acc[0][1] += x0 * wv.y; acc[0][2] += x0 * wv.z; acc[0][3] += x0 * wv.w;
            acc[1][0] += x1 * wv.x; acc[1][1] += x1 * wv.y; acc[1][2] += x1 * wv.z; acc[1][3] += x1 * wv.w;
            acc[2][0] += x2 * wv.x; acc[2][1] += x2 * wv.y; acc[2][2] += x2 * wv.z; acc[2][3] += x2 * wv.w;
            acc[3][0] += x3 * wv.x; acc[3][1] += x3 * wv.y; acc[3][2] += x3 * wv.z; acc[3][3] += x3 * wv.w;
        }
    }

    float a_s[4], a_d[4];
#pragma unroll
    for (int c = 0; c < 4; c++) {
        a_s[c] = a_src1[tc * 4 + c];
        a_d[c] = a_dst1[tc * 4 + c];
    }
#pragma unroll
    for (int r = 0; r < 4; r++) {
        int n = nb + tr * 4 + r;
        bool ok = (n < N_NODES);
        if (ok) {
            __half2 p0 = __floats2half2_rn(acc[r][0], acc[r][1]);
            __half2 p1 = __floats2half2_rn(acc[r][2], acc[r][3]);
            uint2 u;
            u.x = *(unsigned*)&p0;
            u.y = *(unsigned*)&p1;
            *(uint2*)(d_h1h + n * 64 + tc * 4) = u;
        }
        float cs = acc[r][0] * a_s[0] + acc[r][1] * a_s[1] + acc[r][2] * a_s[2] + acc[r][3] * a_s[3];
        float cd = acc[r][0] * a_d[0] + acc[r][1] * a_d[1] + acc[r][2] * a_d[2] + acc[r][3] * a_d[3];
        cs += __shfl_xor_sync(0xffffffffu, cs, 1);
        cd += __shfl_xor_sync(0xffffffffu, cd, 1);
        if (((tc & 1) == 0) && ok) {
            int h = tc >> 1;
            d_als1[n * 8 + h] = cs;
            d_ald1[n * 8 + h] = cd;
        }
    }
}

// ================= L1 aggregation: warp per dst node, single pass (R8 proven form) =================
__global__ __launch_bounds__(256) void l1_agg(const float* __restrict__ b1) {
    int gw   = (blockIdx.x * 256 + threadIdx.x) >> 5;
    int lane = threadIdx.x & 31;
    if (gw >= N_NODES) return;
    int dst = gw;
    int beg = d_rowptr[dst], end = d_rowptr[dst + 1];
    int h8 = lane & 7;
    int myhead = lane >> 2;
    float ald_h = d_ald1[dst * 8 + h8];

    float sum = 0.f;
    float acc0 = 0.f, acc1 = 0.f;
#pragma unroll 2
    for (int i = beg; i < end; i++) {
        int src = d_esrc[i];
        float e_h = __expf(lrelu(d_als1[src * 8 + h8] + ald_h));
        sum += e_h;
        float alpha = __shfl_sync(0xffffffffu, e_h, myhead);
        __half2 hv = *(const __half2*)(d_h1h + src * 64 + lane * 2);
        float2 hf = __half22float2(hv);
        acc0 += hf.x * alpha;
        acc1 += hf.y * alpha;
    }
    float inv = 1.f / (__shfl_sync(0xffffffffu, sum, myhead) + 1e-16f);
    float r0 = acc0 * inv + b1[lane * 2];
    float r1 = acc1 * inv + b1[lane * 2 + 1];
    r0 = r0 > 0.f ? r0 : 0.f;
    r1 = r1 > 0.f ? r1 : 0.f;
    *(__half2*)(d_out1h + dst * 64 + lane * 2) = __floats2half2_rn(r0, r1);
}

// ================= K5: h2 = out1 @ W2 (100000x64 @ 64x128), register-tiled, fp16 input =================
#define RPB2 64
__global__ __launch_bounds__(256) void k5_gemm(const float* __restrict__ W2,
                                               const float* __restrict__ a_src2,
                                               const float* __restrict__ a_dst2) {
    __shared__ float xs[RPB2][32];
    __shared__ float Ws[32][128];
    int t  = threadIdx.x;
    int nb = blockIdx.x * RPB2;
    int tr = t >> 4;
    int tc = t & 15;
    float acc[4][8];
#pragma unroll
    for (int r = 0; r < 4; r++)
#pragma unroll
        for (int c = 0; c < 8; c++) acc[r][c] = 0.f;

    for (int p = 0; p < 2; p++) {
        __syncthreads();
        {
            // x panel: 64 rows x 32 fp16 cols; each thread loads 8 halves (16B)
            int row = t >> 2;
            int seg = t & 3;
            int n = nb + row;
            float* xd = &xs[row][seg * 8];
            if (n < N_NODES) {
                union { uint4 u; __half2 h[4]; } v;
                v.u = *(const uint4*)(d_out1h + n * 64 + p * 32 + seg * 8);
#pragma unroll
                for (int j = 0; j < 4; j++) {
                    float2 f = __half22float2(v.h[j]);
                    xd[j * 2] = f.x;
                    xd[j * 2 + 1] = f.y;
                }
            } else {
#pragma unroll
                for (int j = 0; j < 8; j++) xd[j] = 0.f;
            }
            const float4* Wg = (const float4*)(W2 + (p * 32) * 128);
            float4* Wd = (float4*)&Ws[0][0];
            for (int i = t; i < 32 * 128 / 4; i += 256) Wd[i] = Wg[i];
        }
        __syncthreads();
#pragma unroll 2
        for (int kk = 0; kk < 32; kk++) {
            float4 wv0 = *(const float4*)&Ws[kk][tc * 8];
            float4 wv1 = *(const float4*)&Ws[kk][tc * 8 + 4];
            float x0 = xs[tr * 4 + 0][kk];
            float x1 = xs[tr * 4 + 1][kk];
            float x2 = xs[tr * 4 + 2][kk];
            float x3 = xs[tr * 4 + 3][kk];
#define K5STEP(r, xv) \
            acc[r][0] += xv * wv0.x; acc[r][1] += xv * wv0.y; \
            acc[r][2] += xv * wv0.z; acc[r][3] += xv * wv0.w; \
            acc[r][4] += xv * wv1.x; acc[r][5] += xv * wv1.y; \
            acc[r][6] += xv * wv1.z; acc[r][7] += xv * wv1.w;
            K5STEP(0, x0) K5STEP(1, x1) K5STEP(2, x2) K5STEP(3, x3)
#undef K5STEP
        }
    }

    float a_s[8], a_d[8];
#pragma unroll
    for (int c = 0; c < 8; c++) {
        a_s[c] = a_src2[tc * 8 + c];
        a_d[c] = a_dst2[tc * 8 + c];
    }
#pragma unroll
    for (int r = 0; r < 4; r++) {
        int n = nb + tr * 4 + r;
        bool ok = (n < N_NODES);
        if (ok) {
            __half2 p0 = __floats2half2_rn(acc[r][0], acc[r][1]);
            __half2 p1 = __floats2half2_rn(acc[r][2], acc[r][3]);
            __half2 p2 = __floats2half2_rn(acc[r][4], acc[r][5]);
            __half2 p3 = __floats2half2_rn(acc[r][6], acc[r][7]);
            uint4 u;
            u.x = *(unsigned*)&p0;
            u.y = *(unsigned*)&p1;
            u.z = *(unsigned*)&p2;
            u.w = *(unsigned*)&p3;
            *(uint4*)(d_h2h + n * 128 + tc * 8) = u;
        }
        float cs = 0.f, cd = 0.f;
#pragma unroll
        for (int c = 0; c < 8; c++) {
            cs += acc[r][c] * a_s[c];
            cd += acc[r][c] * a_d[c];
        }
#pragma unroll
        for (int off = 1; off < 16; off <<= 1) {
            cs += __shfl_xor_sync(0xffffffffu, cs, off);
            cd += __shfl_xor_sync(0xffffffffu, cd, off);
        }
        if (tc == 0 && ok) {
            d_als2[n] = cs;
            d_ald2[n] = cd;
        }
    }
}

// ================= L2 aggregation: warp per dst node, single pass (R8 proven form) =================
__global__ __launch_bounds__(256) void l2_agg() {
    int gw   = (blockIdx.x * 256 + threadIdx.x) >> 5;
    int lane = threadIdx.x & 31;
    if (gw >= N_NODES) return;
    int dst = gw;
    int beg = d_rowptr[dst], end = d_rowptr[dst + 1];
    float ald = d_ald2[dst];

    float sum = 0.f;
    float4 acc = make_float4(0.f, 0.f, 0.f, 0.f);
#pragma unroll 2
    for (int i = beg; i < end; i++) {
        int src = d_esrc[i];
        float e = __expf(lrelu(d_als2[src] + ald));
        sum += e;
        __half2 hv[2];
        *(uint2*)hv = *(const uint2*)(d_h2h + src * 128 + lane * 4);
        float2 h0 = __half22float2(hv[0]);
        float2 h1 = __half22float2(hv[1]);
        acc.x += h0.x * e;
        acc.y += h0.y * e;
        acc.z += h1.x * e;
        acc.w += h1.y * e;
    }
    float inv = 1.f / (sum + 1e-16f);
    acc.x *= inv; acc.y *= inv; acc.z *= inv; acc.w *= inv;
    *(float4*)(d_out2 + dst * 128 + lane * 4) = acc;
}

// ================= K8: pool + FC + log_softmax (monolithic, 256 threads / graph) =================
__global__ __launch_bounds__(256) void k8_pool(const int* __restrict__ batch,
                                               const float* __restrict__ b2,
                                               const float* __restrict__ fc_w,
                                               const float* __restrict__ fc_b,
                                               float* __restrict__ out) {
    int g    = blockIdx.x;
    int tid  = threadIdx.x;
    int t    = tid & 127;
    int half = tid >> 7;
    int lo, hi;
    {
        int a = 0, b = N_NODES;
        while (a < b) { int m = (a + b) >> 1; if (batch[m] < g) a = m + 1; else b = m; }
        lo = a;
        a = lo; b = N_NODES;
        while (a < b) { int m = (a + b) >> 1; if (batch[m] < g + 1) a = m + 1; else b = m; }
        hi = a;
    }
    int cnt = hi - lo;
    float acc = 0.f;
    for (int n = lo + half; n < hi; n += 2) acc += d_out2[n * 128 + t];
    __shared__ float sacc[2][128];
    sacc[half][t] = acc;
    __syncthreads();
    __shared__ float sp[128];
    if (tid < 128) {
        float total = sacc[0][t] + sacc[1][t];
        float inv = 1.f / (float)max(cnt, 1);
        sp[t] = (total + (float)cnt * b2[t]) * inv;
    }
    __syncthreads();
    __shared__ float sl[N_CLASSES];
    if (tid < N_CLASSES) {
        float v = fc_b[tid];
        for (int k = 0; k < 128; k++) v += sp[k] * fc_w[k * N_CLASSES + tid];
        sl[tid] = v;
    }
    __syncthreads();
    __shared__ float s_m, s_lse;
    if (tid == 0) {
        float m = sl[0];
        for (int c = 1; c < N_CLASSES; c++) m = fmaxf(m, sl[c]);
        float se = 0.f;
        for (int c = 0; c < N_CLASSES; c++) se += expf(sl[c] - m);
        s_m = m;
        s_lse = logf(se);
    }
    __syncthreads();
    if (tid < N_CLASSES) out[g * N_CLASSES + tid] = sl[tid] - s_m - s_lse;
}

// ================= launch =================
static cudaStream_t g_side = nullptr;
static cudaEvent_t  g_fork = nullptr, g_join = nullptr;

extern "C" void kernel_launch(void* const* d_in, const int* in_sizes, int n_in,
                              void* d_out, int out_size) {
    const float* x      = (const float*)d_in[0];
    const int*   ei     = (const int*)d_in[1];
    const int*   batch  = (const int*)d_in[2];
    const float* W1     = (const float*)d_in[3];
    const float* a_src1 = (const float*)d_in[4];
    const float* a_dst1 = (const float*)d_in[5];
    const float* b1     = (const float*)d_in[6];
    const float* W2     = (const float*)d_in[7];
    const float* a_src2 = (const float*)d_in[8];
    const float* a_dst2 = (const float*)d_in[9];
    const float* b2     = (const float*)d_in[10];
    const float* fc_w   = (const float*)d_in[11];
    const float* fc_b   = (const float*)d_in[12];
    float* out = (float*)d_out;

    if (g_side == nullptr) {
        cudaStreamCreateWithFlags(&g_side, cudaStreamNonBlocking);
        cudaEventCreateWithFlags(&g_fork, cudaEventDisableTiming);
        cudaEventCreateWithFlags(&g_join, cudaEventDisableTiming);
    }

    const int WB = (N_NODES * 32 + 255) / 256;
    const int GB = (N_NODES + RPB1 - 1) / RPB1;
    const int HB = (N_EDGES / 2 + 255) / 256;
    const int SB = (N_EDGES / 2 + N_NODES + 255) / 256;

    // Fork: CSR build on side stream, concurrent with k1_gemm on main stream.
    cudaEventRecord(g_fork, 0);
    cudaStreamWaitEvent(g_side, g_fork, 0);

    k_zero_deg<<<NB_SCAN, SCAN_B, 0, g_side>>>();
    k_hist<<<HB, 256, 0, g_side>>>(ei);
    k_scan_all<<<1, SCAN_B, 0, g_side>>>();
    k_scatter<<<SB, 256, 0, g_side>>>(ei);
    cudaEventRecord(g_join, g_side);

    // main stream: layer-1 GEMM (independent of CSR)
    k1_gemm<<<GB, 256>>>(x, W1, a_src1, a_dst1);

    // join: everything below needs both branches
    cudaStreamWaitEvent(0, g_join, 0);

    l1_agg<<<WB, 256>>>(b1);
    k5_gemm<<<GB, 256>>>(W2, a_src2, a_dst2);
    l2_agg<<<WB, 256>>>();
    k8_pool<<<N_GRAPHS, 256>>>(batch, b2, fc_w, fc_b, out);
}

// round 16
// speedup vs baseline: 2.3016x; 2.3016x over previous
#include <cuda_runtime.h>
#include <cuda_fp16.h>

// Problem constants
#define N_NODES   100000
#define N_EDGES   1600000
#define E_TOT     (N_EDGES + N_NODES)   // with self-loops
#define N_FEAT    128
#define N_CLASSES 10
#define N_GRAPHS  256

#define SCAN_B    512
#define NB_SCAN   ((N_NODES + SCAN_B - 1) / SCAN_B)   // 196

// ---------------- device scratch ----------------
__device__ __align__(16) __half d_h1h[N_NODES * 64];    // layer1 features (gather-only)
__device__ __align__(16) float  d_als1[N_NODES * 8];
__device__ __align__(16) float  d_ald1[N_NODES * 8];
__device__ __align__(16) __half d_out1h[N_NODES * 64];  // layer1 output (k5 input, fp16)
__device__ __align__(16) __half d_h2h[N_NODES * 128];   // layer2 features (gather-only)
__device__ __align__(16) float  d_als2[N_NODES];
__device__ __align__(16) float  d_ald2[N_NODES];
__device__ __align__(16) float  d_out2[N_NODES * 128];

// CSR scratch
__device__ int d_deg   [N_NODES];
__device__ int d_incl  [N_NODES];
__device__ int d_bsum  [256];
__device__ int d_bofs  [256];
__device__ int d_rowptr[N_NODES + 1];
__device__ int d_wofs  [N_NODES];
__device__ int d_esrc  [E_TOT];

__device__ __forceinline__ float lrelu(float v) { return v > 0.f ? v : 0.2f * v; }

// ================= CSR build (R14 proven multi-block form) =================
__global__ void k_zero_deg() {
    int i = blockIdx.x * SCAN_B + threadIdx.x;
    if (i < N_NODES) d_deg[i] = 0;
}

__global__ void k_hist(const int* __restrict__ ei) {
    int i = blockIdx.x * 256 + threadIdx.x;
    int e = i * 2;
    if (e >= N_EDGES) return;
    int2 d = *(const int2*)(ei + N_EDGES + e);
    atomicAdd(&d_deg[d.x], 1);
    atomicAdd(&d_deg[d.y], 1);
}

__global__ __launch_bounds__(SCAN_B) void k_scan1() {
    __shared__ int s[SCAN_B];
    int i = blockIdx.x * SCAN_B + threadIdx.x;
    int v = (i < N_NODES) ? (d_deg[i] + 1) : 0;   // +1 = self-loop
    s[threadIdx.x] = v;
    __syncthreads();
#pragma unroll
    for (int off = 1; off < SCAN_B; off <<= 1) {
        int t = (threadIdx.x >= off) ? s[threadIdx.x - off] : 0;
        __syncthreads();
        s[threadIdx.x] += t;
        __syncthreads();
    }
    if (i < N_NODES) d_incl[i] = s[threadIdx.x];
    if (threadIdx.x == SCAN_B - 1) d_bsum[blockIdx.x] = s[SCAN_B - 1];
}

__global__ __launch_bounds__(256) void k_scan2() {
    __shared__ int s[256];
    int t = threadIdx.x;
    int v = (t < NB_SCAN) ? d_bsum[t] : 0;
    s[t] = v;
    __syncthreads();
#pragma unroll
    for (int off = 1; off < 256; off <<= 1) {
        int u = (t >= off) ? s[t - off] : 0;
        __syncthreads();
        s[t] += u;
        __syncthreads();
    }
    if (t < NB_SCAN) d_bofs[t] = s[t] - v;   // exclusive
}

__global__ __launch_bounds__(SCAN_B) void k_scan3() {
    int i = blockIdx.x * SCAN_B + threadIdx.x;
    if (i < N_NODES) {
        int v = d_incl[i] + d_bofs[blockIdx.x];
        d_rowptr[i + 1] = v;
        if (i + 1 < N_NODES) d_wofs[i + 1] = v;
    }
    if (i == 0) { d_rowptr[0] = 0; d_wofs[0] = 0; }
}

__global__ void k_scatter(const int* __restrict__ ei) {
    int i = blockIdx.x * 256 + threadIdx.x;
    int e = i * 2;
    if (e < N_EDGES) {
        int2 sv = *(const int2*)(ei + e);
        int2 dv = *(const int2*)(ei + N_EDGES + e);
        int p0 = atomicAdd(&d_wofs[dv.x], 1);
        d_esrc[p0] = sv.x;
        int p1 = atomicAdd(&d_wofs[dv.y], 1);
        d_esrc[p1] = sv.y;
    } else {
        int n = i - N_EDGES / 2;
        if (n < N_NODES) {
            int p = atomicAdd(&d_wofs[n], 1);
            d_esrc[p] = n;
        }
    }
}

// ================= K1: h1 = x @ W1 (100000x128 @ 128x64), register-tiled =================
#define RPB1 64
__global__ __launch_bounds__(256) void k1_gemm(const float* __restrict__ x,
                                               const float* __restrict__ W1,
                                               const float* __restrict__ a_src1,
                                               const float* __restrict__ a_dst1) {
    __shared__ float xs[RPB1][64];
    __shared__ float Ws[64][64];
    int t  = threadIdx.x;
    int nb = blockIdx.x * RPB1;
    int tr = t >> 4;
    int tc = t & 15;
    float acc[4][4];
#pragma unroll
    for (int r = 0; r < 4; r++)
#pragma unroll
        for (int c = 0; c < 4; c++) acc[r][c] = 0.f;

    for (int p = 0; p < 2; p++) {
        __syncthreads();
        {
            int nl = t >> 2;
            int j0 = (t & 3) * 4;
            int n = nb + nl;
            float4* xd = (float4*)&xs[nl][0];
            if (n < N_NODES) {
                const float4* xg = (const float4*)(x + n * 128 + p * 64);
#pragma unroll
                for (int j = 0; j < 4; j++) xd[j0 + j] = xg[j0 + j];
            } else {
                float4 z = make_float4(0.f, 0.f, 0.f, 0.f);
#pragma unroll
                for (int j = 0; j < 4; j++) xd[j0 + j] = z;
            }
            const float4* Wg = (const float4*)(W1 + (p * 64) * 64);
            float4* Wd = (float4*)&Ws[0][0];
            for (int i = t; i < 64 * 64 / 4; i += 256) Wd[i] = Wg[i];
        }
        __syncthreads();
#pragma unroll 2
        for (int kk = 0; kk < 64; kk++) {
            float4 wv = *(const float4*)&Ws[kk][tc * 4];
            float x0 = xs[tr * 4 + 0][kk];
            float x1 = xs[tr * 4 + 1][kk];
            float x2 = xs[tr * 4 + 2][kk];
            float x3 = xs[tr * 4 + 3][kk];
            acc[0][0] += x0 * wv.x; acc[0][1] += x0 * wv.y; acc[0][2] += x0 * wv.z; acc[0][3] += x0 * wv.w;
            acc[1][0] += x1 * wv.x; acc[1][1] += x1 * wv.y; acc[1][2] += x1 * wv.z; acc[1][3] += x1 * wv.w;
            acc[2][0] += x2 * wv.x; acc[2][1] += x2 * wv.y; acc[2][2] += x2 * wv.z; acc[2][3] += x2 * wv.w;
            acc[3][0] += x3 * wv.x; acc[3][1] += x3 * wv.y; acc[3][2] += x3 * wv.z; acc[3][3] += x3 * wv.w;
        }
    }

    float a_s[4], a_d[4];
#pragma unroll
    for (int c = 0; c < 4; c++) {
        a_s[c] = a_src1[tc * 4 + c];
        a_d[c] = a_dst1[tc * 4 + c];
    }
#pragma unroll
    for (int r = 0; r < 4; r++) {
        int n = nb + tr * 4 + r;
        bool ok = (n < N_NODES);
        if (ok) {
            __half2 p0 = __floats2half2_rn(acc[r][0], acc[r][1]);
            __half2 p1 = __floats2half2_rn(acc[r][2], acc[r][3]);
            uint2 u;
            u.x = *(unsigned*)&p0;
            u.y = *(unsigned*)&p1;
            *(uint2*)(d_h1h + n * 64 + tc * 4) = u;
        }
        float cs = acc[r][0] * a_s[0] + acc[r][1] * a_s[1] + acc[r][2] * a_s[2] + acc[r][3] * a_s[3];
        float cd = acc[r][0] * a_d[0] + acc[r][1] * a_d[1] + acc[r][2] * a_d[2] + acc[r][3] * a_d[3];
        cs += __shfl_xor_sync(0xffffffffu, cs, 1);
        cd += __shfl_xor_sync(0xffffffffu, cd, 1);
        if (((tc & 1) == 0) && ok) {
            int h = tc >> 1;
            d_als1[n * 8 + h] = cs;
            d_ald1[n * 8 + h] = cd;
        }
    }
}

// ================= L1 aggregation: warp per dst node, single pass (R8 proven form) =================
__global__ __launch_bounds__(256) void l1_agg(const float* __restrict__ b1) {
    int gw   = (blockIdx.x * 256 + threadIdx.x) >> 5;
    int lane = threadIdx.x & 31;
    if (gw >= N_NODES) return;
    int dst = gw;
    int beg = d_rowptr[dst], end = d_rowptr[dst + 1];
    int h8 = lane & 7;
    int myhead = lane >> 2;
    float ald_h = d_ald1[dst * 8 + h8];

    float sum = 0.f;
    float acc0 = 0.f, acc1 = 0.f;
#pragma unroll 2
    for (int i = beg; i < end; i++) {
        int src = d_esrc[i];
        float e_h = __expf(lrelu(d_als1[src * 8 + h8] + ald_h));
        sum += e_h;
        float alpha = __shfl_sync(0xffffffffu, e_h, myhead);
        __half2 hv = *(const __half2*)(d_h1h + src * 64 + lane * 2);
        float2 hf = __half22float2(hv);
        acc0 += hf.x * alpha;
        acc1 += hf.y * alpha;
    }
    float inv = 1.f / (__shfl_sync(0xffffffffu, sum, myhead) + 1e-16f);
    float r0 = acc0 * inv + b1[lane * 2];
    float r1 = acc1 * inv + b1[lane * 2 + 1];
    r0 = r0 > 0.f ? r0 : 0.f;
    r1 = r1 > 0.f ? r1 : 0.f;
    *(__half2*)(d_out1h + dst * 64 + lane * 2) = __floats2half2_rn(r0, r1);
}

// ================= K5: h2 = out1 @ W2 (100000x64 @ 64x128), register-tiled, fp16 input =================
#define RPB2 64
__global__ __launch_bounds__(256) void k5_gemm(const float* __restrict__ W2,
                                               const float* __restrict__ a_src2,
                                               const float* __restrict__ a_dst2) {
    __shared__ float xs[RPB2][32];
    __shared__ float Ws[32][128];
    int t  = threadIdx.x;
    int nb = blockIdx.x * RPB2;
    int tr = t >> 4;
    int tc = t & 15;
    float acc[4][8];
#pragma unroll
    for (int r = 0; r < 4; r++)
#pragma unroll
        for (int c = 0; c < 8; c++) acc[r][c] = 0.f;

    for (int p = 0; p < 2; p++) {
        __syncthreads();
        {
            // x panel: 64 rows x 32 fp16 cols; each thread loads 8 halves (16B)
            int row = t >> 2;
            int seg = t & 3;
            int n = nb + row;
            float* xd = &xs[row][seg * 8];
            if (n < N_NODES) {
                union { uint4 u; __half2 h[4]; } v;
                v.u = *(const uint4*)(d_out1h + n * 64 + p * 32 + seg * 8);
#pragma unroll
                for (int j = 0; j < 4; j++) {
                    float2 f = __half22float2(v.h[j]);
                    xd[j * 2] = f.x;
                    xd[j * 2 + 1] = f.y;
                }
            } else {
#pragma unroll
                for (int j = 0; j < 8; j++) xd[j] = 0.f;
            }
            const float4* Wg = (const float4*)(W2 + (p * 32) * 128);
            float4* Wd = (float4*)&Ws[0][0];
            for (int i = t; i < 32 * 128 / 4; i += 256) Wd[i] = Wg[i];
        }
        __syncthreads();
#pragma unroll 2
        for (int kk = 0; kk < 32; kk++) {
            float4 wv0 = *(const float4*)&Ws[kk][tc * 8];
            float4 wv1 = *(const float4*)&Ws[kk][tc * 8 + 4];
            float x0 = xs[tr * 4 + 0][kk];
            float x1 = xs[tr * 4 + 1][kk];
            float x2 = xs[tr * 4 + 2][kk];
            float x3 = xs[tr * 4 + 3][kk];
#define K5STEP(r, xv) \
            acc[r][0] += xv * wv0.x; acc[r][1] += xv * wv0.y; \
            acc[r][2] += xv * wv0.z; acc[r][3] += xv * wv0.w; \
            acc[r][4] += xv * wv1.x; acc[r][5] += xv * wv1.y; \
            acc[r][6] += xv * wv1.z; acc[r][7] += xv * wv1.w;
            K5STEP(0, x0) K5STEP(1, x1) K5STEP(2, x2) K5STEP(3, x3)
#undef K5STEP
        }
    }

    float a_s[8], a_d[8];
#pragma unroll
    for (int c = 0; c < 8; c++) {
        a_s[c] = a_src2[tc * 8 + c];
        a_d[c] = a_dst2[tc * 8 + c];
    }
#pragma unroll
    for (int r = 0; r < 4; r++) {
        int n = nb + tr * 4 + r;
        bool ok = (n < N_NODES);
        if (ok) {
            __half2 p0 = __floats2half2_rn(acc[r][0], acc[r][1]);
            __half2 p1 = __floats2half2_rn(acc[r][2], acc[r][3]);
            __half2 p2 = __floats2half2_rn(acc[r][4], acc[r][5]);
            __half2 p3 = __floats2half2_rn(acc[r][6], acc[r][7]);
            uint4 u;
            u.x = *(unsigned*)&p0;
            u.y = *(unsigned*)&p1;
            u.z = *(unsigned*)&p2;
            u.w = *(unsigned*)&p3;
            *(uint4*)(d_h2h + n * 128 + tc * 8) = u;
        }
        float cs = 0.f, cd = 0.f;
#pragma unroll
        for (int c = 0; c < 8; c++) {
            cs += acc[r][c] * a_s[c];
            cd += acc[r][c] * a_d[c];
        }
#pragma unroll
        for (int off = 1; off < 16; off <<= 1) {
            cs += __shfl_xor_sync(0xffffffffu, cs, off);
            cd += __shfl_xor_sync(0xffffffffu, cd, off);
        }
        if (tc == 0 && ok) {
            d_als2[n] = cs;
            d_ald2[n] = cd;
        }
    }
}

// ================= L2 aggregation: warp per dst node, single pass (R8 proven form) =================
__global__ __launch_bounds__(256) void l2_agg() {
    int gw   = (blockIdx.x * 256 + threadIdx.x) >> 5;
    int lane = threadIdx.x & 31;
    if (gw >= N_NODES) return;
    int dst = gw;
    int beg = d_rowptr[dst], end = d_rowptr[dst + 1];
    float ald = d_ald2[dst];

    float sum = 0.f;
    float4 acc = make_float4(0.f, 0.f, 0.f, 0.f);
#pragma unroll 2
    for (int i = beg; i < end; i++) {
        int src = d_esrc[i];
        float e = __expf(lrelu(d_als2[src] + ald));
        sum += e;
        __half2 hv[2];
        *(uint2*)hv = *(const uint2*)(d_h2h + src * 128 + lane * 4);
        float2 h0 = __half22float2(hv[0]);
        float2 h1 = __half22float2(hv[1]);
        acc.x += h0.x * e;
        acc.y += h0.y * e;
        acc.z += h1.x * e;
        acc.w += h1.y * e;
    }
    float inv = 1.f / (sum + 1e-16f);
    acc.x *= inv; acc.y *= inv; acc.z *= inv; acc.w *= inv;
    *(float4*)(d_out2 + dst * 128 + lane * 4) = acc;
}

// ================= K8: pool + FC + log_softmax (monolithic, 256 threads / graph) =================
__global__ __launch_bounds__(256) void k8_pool(const int* __restrict__ batch,
                                               const float* __restrict__ b2,
                                               const float* __restrict__ fc_w,
                                               const float* __restrict__ fc_b,
                                               float* __restrict__ out) {
    int g    = blockIdx.x;
    int tid  = threadIdx.x;
    int t    = tid & 127;
    int half = tid >> 7;
    int lo, hi;
    {
        int a = 0, b = N_NODES;
        while (a < b) { int m = (a + b) >> 1; if (batch[m] < g) a = m + 1; else b = m; }
        lo = a;
        a = lo; b = N_NODES;
        while (a < b) { int m = (a + b) >> 1; if (batch[m] < g + 1) a = m + 1; else b = m; }
        hi = a;
    }
    int cnt = hi - lo;
    float acc = 0.f;
    for (int n = lo + half; n < hi; n += 2) acc += d_out2[n * 128 + t];
    __shared__ float sacc[2][128];
    sacc[half][t] = acc;
    __syncthreads();
    __shared__ float sp[128];
    if (tid < 128) {
        float total = sacc[0][t] + sacc[1][t];
        float inv = 1.f / (float)max(cnt, 1);
        sp[t] = (total + (float)cnt * b2[t]) * inv;
    }
    __syncthreads();
    __shared__ float sl[N_CLASSES];
    if (tid < N_CLASSES) {
        float v = fc_b[tid];
        for (int k = 0; k < 128; k++) v += sp[k] * fc_w[k * N_CLASSES + tid];
        sl[tid] = v;
    }
    __syncthreads();
    __shared__ float s_m, s_lse;
    if (tid == 0) {
        float m = sl[0];
        for (int c = 1; c < N_CLASSES; c++) m = fmaxf(m, sl[c]);
        float se = 0.f;
        for (int c = 0; c < N_CLASSES; c++) se += expf(sl[c] - m);
        s_m = m;
        s_lse = logf(se);
    }
    __syncthreads();
    if (tid < N_CLASSES) out[g * N_CLASSES + tid] = sl[tid] - s_m - s_lse;
}

// ================= launch =================
static cudaStream_t g_side = nullptr;
static cudaEvent_t  g_fork = nullptr, g_join = nullptr;

extern "C" void kernel_launch(void* const* d_in, const int* in_sizes, int n_in,
                              void* d_out, int out_size) {
    const float* x      = (const float*)d_in[0];
    const int*   ei     = (const int*)d_in[1];
    const int*   batch  = (const int*)d_in[2];
    const float* W1     = (const float*)d_in[3];
    const float* a_src1 = (const float*)d_in[4];
    const float* a_dst1 = (const float*)d_in[5];
    const float* b1     = (const float*)d_in[6];
    const float* W2     = (const float*)d_in[7];
    const float* a_src2 = (const float*)d_in[8];
    const float* a_dst2 = (const float*)d_in[9];
    const float* b2     = (const float*)d_in[10];
    const float* fc_w   = (const float*)d_in[11];
    const float* fc_b   = (const float*)d_in[12];
    float* out = (float*)d_out;

    if (g_side == nullptr) {
        cudaStreamCreateWithFlags(&g_side, cudaStreamNonBlocking);
        cudaEventCreateWithFlags(&g_fork, cudaEventDisableTiming);
        cudaEventCreateWithFlags(&g_join, cudaEventDisableTiming);
    }

    const int WB = (N_NODES * 32 + 255) / 256;
    const int GB = (N_NODES + RPB1 - 1) / RPB1;
    const int HB = (N_EDGES / 2 + 255) / 256;
    const int SB = (N_EDGES / 2 + N_NODES + 255) / 256;

    // Fork: CSR build on side stream, concurrent with k1_gemm on main stream.
    cudaEventRecord(g_fork, 0);
    cudaStreamWaitEvent(g_side, g_fork, 0);

    k_zero_deg<<<NB_SCAN, SCAN_B, 0, g_side>>>();
    k_hist<<<HB, 256, 0, g_side>>>(ei);
    k_scan1<<<NB_SCAN, SCAN_B, 0, g_side>>>();
    k_scan2<<<1, 256, 0, g_side>>>();
    k_scan3<<<NB_SCAN, SCAN_B, 0, g_side>>>();
    k_scatter<<<SB, 256, 0, g_side>>>(ei);
    cudaEventRecord(g_join, g_side);

    // main stream: layer-1 GEMM (independent of CSR)
    k1_gemm<<<GB, 256>>>(x, W1, a_src1, a_dst1);

    // join: everything below needs both branches
    cudaStreamWaitEvent(0, g_join, 0);

    l1_agg<<<WB, 256>>>(b1);
    k5_gemm<<<GB, 256>>>(W2, a_src2, a_dst2);
    l2_agg<<<WB, 256>>>();
    k8_pool<<<N_GRAPHS, 256>>>(batch, b2, fc_w, fc_b, out);
}